// round 16
// baseline (speedup 1.0000x reference)
#include <cuda_runtime.h>
#include <cuda_fp16.h>
#include <math_constants.h>
#include <cstdint>
#include <cstddef>

#define NB 32
#define CC 512
#define PP 1024
#define SS 2048
#define NK 10
#define KC 10     // candidates per position (= 2 x KT)
#define KT 5      // per-thread list depth

#define XSS 136   // x smem tile row stride (fp16)
#define CBS 40    // cb smem tile row stride (fp16)

// static device scratch
__device__ __half g_xh[(size_t)NB * CC * PP];    // fp16 x, layout [n][c][p]
__device__ __half g_cbh[(size_t)SS * CC];        // fp16 cb, [s][c]
__device__ float  g_c2[SS];
__device__ int    g_cand[(size_t)NB * PP * KC];  // approx top-KC indices
__device__ int    g_idx[NB * PP];
__device__ double g_acc_cb;
__device__ double g_acc_commit;

// ---------------------------------------------------------------------------
__device__ __forceinline__ uint32_t cvta_s(const void* p) {
    return (uint32_t)__cvta_generic_to_shared(p);
}
__device__ __forceinline__ void cpa16(uint32_t d, const void* s) {
    asm volatile("cp.async.ca.shared.global [%0],[%1],16;" ::"r"(d), "l"(s));
}
__device__ __forceinline__ void cpcommit() {
    asm volatile("cp.async.commit_group;");
}
__device__ __forceinline__ void cpwait1() {
    asm volatile("cp.async.wait_group 1;");
}
__device__ __forceinline__ void cpwait0() {
    asm volatile("cp.async.wait_group 0;");
}
__device__ __forceinline__ void ldsm4t(uint32_t* d, uint32_t a) {
    asm volatile("ldmatrix.sync.aligned.m8n8.x4.trans.shared.b16 {%0,%1,%2,%3},[%4];"
                 : "=r"(d[0]), "=r"(d[1]), "=r"(d[2]), "=r"(d[3]) : "r"(a));
}
__device__ __forceinline__ void ldsm4(uint32_t* d, uint32_t a) {
    asm volatile("ldmatrix.sync.aligned.m8n8.x4.shared.b16 {%0,%1,%2,%3},[%4];"
                 : "=r"(d[0]), "=r"(d[1]), "=r"(d[2]), "=r"(d[3]) : "r"(a));
}
// fp16-accumulate mma: D,C = 2 x .f16x2 regs
__device__ __forceinline__ void mma_f16a(uint32_t* c, const uint32_t* a, const uint32_t* b) {
    asm volatile("mma.sync.aligned.m16n8k16.row.col.f16.f16.f16.f16 "
                 "{%0,%1},{%2,%3,%4,%5},{%6,%7},{%0,%1};"
                 : "+r"(c[0]), "+r"(c[1])
                 : "r"(a[0]), "r"(a[1]), "r"(a[2]), "r"(a[3]), "r"(b[0]), "r"(b[1]));
}
__device__ __forceinline__ uint32_t pack_hf2(__half a, __half b) {
    return (uint32_t)__half_as_ushort(a) | ((uint32_t)__half_as_ushort(b) << 16);
}

// ---------------------------------------------------------------------------
// x prep: pure streaming fp32 -> fp16 convert (no transpose; g_xt removed)
__global__ void k_prep_x(const float* __restrict__ x) {
    size_t i = ((size_t)blockIdx.x * blockDim.x + threadIdx.x) * 4;
    float4 v = *(const float4*)(x + i);
    __half2 h01 = __floats2half2_rn(v.x, v.y);
    __half2 h23 = __floats2half2_rn(v.z, v.w);
    *(__half2*)(g_xh + i)     = h01;
    *(__half2*)(g_xh + i + 2) = h23;
}

// cb prep: fp16 copy + c2 + zero accumulators
__global__ void k_prep_cb(const float* __restrict__ cb) {
    __shared__ float sm[128];
    int s = blockIdx.x, t = threadIdx.x;
    size_t base = (size_t)s * CC + t * 4;
    float4 v = *(const float4*)(cb + base);
    float a = fmaf(v.x, v.x, fmaf(v.y, v.y, fmaf(v.z, v.z, __fmul_rn(v.w, v.w))));
    __half2 h01 = __floats2half2_rn(v.x, v.y);
    __half2 h23 = __floats2half2_rn(v.z, v.w);
    *(__half2*)(g_cbh + base)     = h01;
    *(__half2*)(g_cbh + base + 2) = h23;
    sm[t] = a;
    __syncthreads();
    for (int off = 64; off > 0; off >>= 1) {
        if (t < off) sm[t] += sm[t + off];
        __syncthreads();
    }
    if (t == 0) {
        g_c2[s] = sm[0];
        if (s == 0) { g_acc_cb = 0.0; g_acc_commit = 0.0; }
    }
}

// ---------------------------------------------------------------------------
// Phase 1: fp16 GEMM (fp16 acc), warp grid 2(p) x 4(s), s-macro-tile 256.
// 256 threads, 2 CTAs/SM, 2-stage cp.async pipeline (R12 structure).
// smem (bytes):
#define SM_XH   0        // 2 x fp16[32][136] = 17408
#define SM_CH   17408    // 2 x fp16[256][40] = 40960
#define SM_C2   58368    // float[256] = 1024
#define SM_DS   59392    // float[64][132] = 33792 (raw xc, one pass of 64 s)
#define SM_TOTAL 93184
#define XSTG 8704
#define CSTG 20480
#define DSS 132

__global__ void __launch_bounds__(256, 2) k_fused() {
    extern __shared__ __align__(16) char smem[];
    float* c2s = (float*)(smem + SM_C2);
    float* ds  = (float*)(smem + SM_DS);

    int n = blockIdx.y, p0 = blockIdx.x << 7;
    int tid = threadIdx.x, lid = tid & 31, wid = tid >> 5;
    int wm = wid & 1, wn = wid >> 1;       // 2 p-strips x 4 s-strips
    int sp = tid & 127, sh = tid >> 7;

    const __half* xh = g_xh + (size_t)n * CC * PP;

    int g8 = lid >> 3, r8 = lid & 7;
    int aoff = ((g8 >> 1) * 8 + r8) * XSS + (g8 & 1) * 8 + wm * 64;
    int boff = ((g8 >> 1) * 8 + r8) * CBS + (g8 & 1) * 8;

    uint32_t xs_b = cvta_s(smem + SM_XH);
    uint32_t cb_b = cvta_s(smem + SM_CH);

    // x stage fill: 8192 B -> 2 x 16B per thread
    int xrow0 = tid >> 4,          xch0 = (tid & 15) << 3;
    int xrow1 = (tid + 256) >> 4,  xch1 = xch0;
    uint32_t dst_x0 = xs_b + (uint32_t)(xrow0 * XSS + xch0) * 2;
    uint32_t dst_x1 = xs_b + (uint32_t)(xrow1 * XSS + xch1) * 2;
    // cb stage fill: 256 rows x 32 k = 16384 B -> 4 x 16B per thread
    int crow = tid >> 2, cch = (tid & 3) << 3;
    uint32_t dst_c0 = cb_b + (uint32_t)((crow +   0) * CBS + cch) * 2;
    uint32_t dst_c1 = cb_b + (uint32_t)((crow +  64) * CBS + cch) * 2;
    uint32_t dst_c2 = cb_b + (uint32_t)((crow + 128) * CBS + cch) * 2;
    uint32_t dst_c3 = cb_b + (uint32_t)((crow + 192) * CBS + cch) * 2;

    auto issue = [&](int G) {                 // G in [0,128)
        int stp = G >> 4, kcp = G & 15, stg = G & 1;
        int k0 = kcp << 5, s0g = stp << 8;
        uint32_t xo = stg ? XSTG : 0u, co = stg ? CSTG : 0u;
        cpa16(dst_x0 + xo, xh + (size_t)(k0 + xrow0) * PP + p0 + xch0);
        cpa16(dst_x1 + xo, xh + (size_t)(k0 + xrow1) * PP + p0 + xch1);
        cpa16(dst_c0 + co, g_cbh + (size_t)(s0g + crow +   0) * CC + k0 + cch);
        cpa16(dst_c1 + co, g_cbh + (size_t)(s0g + crow +  64) * CC + k0 + cch);
        cpa16(dst_c2 + co, g_cbh + (size_t)(s0g + crow + 128) * CC + k0 + cch);
        cpa16(dst_c3 + co, g_cbh + (size_t)(s0g + crow + 192) * CC + k0 + cch);
        cpcommit();
    };

    float val[KT];
    int   idx[KT];
#pragma unroll
    for (int i = 0; i < KT; i++) { val[i] = CUDART_INF_F; idx[i] = 0; }

    issue(0);
    issue(1);

    for (int st = 0; st < 8; ++st) {
        int s0 = st << 8;
        uint32_t acc[4][8][2];
#pragma unroll
        for (int mt = 0; mt < 4; mt++)
#pragma unroll
            for (int nt = 0; nt < 8; nt++) { acc[mt][nt][0] = 0u; acc[mt][nt][1] = 0u; }

        for (int kc = 0; kc < 16; ++kc) {
            int gch = (st << 4) + kc;
            if (gch == 127) cpwait0(); else cpwait1();
            __syncthreads();
            if (kc == 0) c2s[tid] = g_c2[s0 + tid];   // 256 threads, 256 values

            uint32_t xo = (gch & 1) ? XSTG : 0u, co = (gch & 1) ? CSTG : 0u;
#pragma unroll
            for (int ks = 0; ks < 2; ks++) {
                int kb = ks << 4;
                uint32_t Ah[4][4];
#pragma unroll
                for (int mt = 0; mt < 4; mt++)
                    ldsm4t(Ah[mt], xs_b + xo + (uint32_t)(kb * XSS + aoff + mt * 16) * 2);
#pragma unroll
                for (int bg = 0; bg < 4; bg++) {
                    uint32_t Bf[4];
                    int n0 = wn * 64 + bg * 16;
                    ldsm4(Bf, cb_b + co + (uint32_t)(n0 * CBS + kb + boff) * 2);
#pragma unroll
                    for (int q = 0; q < 2; q++) {
                        int nt = bg * 2 + q;
#pragma unroll
                        for (int mt = 0; mt < 4; mt++)
                            mma_f16a(acc[mt][nt], Ah[mt], &Bf[q * 2]);
                    }
                }
            }
            __syncthreads();
            if (gch + 2 < 128) issue(gch + 2);
        }

        // epilogue + scan in 4 passes of 64 s-rows (ds holds 64 rows)
#pragma unroll
        for (int pass = 0; pass < 4; ++pass) {
            if (wn == pass) {
#pragma unroll
                for (int mt = 0; mt < 4; mt++) {
                    int pb = wm * 64 + mt * 16 + (lid >> 2);
#pragma unroll
                    for (int nt = 0; nt < 8; nt++) {
                        int sb = nt * 8 + ((lid & 3) << 1);
                        float2 v01 = __half22float2(*(__half2*)&acc[mt][nt][0]);
                        float2 v23 = __half22float2(*(__half2*)&acc[mt][nt][1]);
                        ds[sb * DSS + pb]           = v01.x;
                        ds[(sb + 1) * DSS + pb]     = v01.y;
                        ds[sb * DSS + pb + 8]       = v23.x;
                        ds[(sb + 1) * DSS + pb + 8] = v23.y;
                    }
                }
            }
            __syncthreads();
            int rbase = sh << 5;
            int sloc  = pass << 6;
#pragma unroll 4
            for (int rr = 0; rr < 32; rr++) {
                int rw = rbase + rr;
                float a = ds[rw * DSS + sp];
                float v = __fmaf_rn(-2.0f, a, c2s[sloc + rw]);   // c2 - 2xc
                if (v < val[KT - 1]) {
                    val[KT - 1] = v; idx[KT - 1] = s0 + sloc + rw;
#pragma unroll
                    for (int i = KT - 1; i > 0; --i) {
                        bool sw = val[i - 1] > val[i];
                        float tv = sw ? val[i - 1] : val[i];
                        float bv = sw ? val[i] : val[i - 1];
                        int   ti = sw ? idx[i - 1] : idx[i];
                        int   bi = sw ? idx[i] : idx[i - 1];
                        val[i - 1] = bv; idx[i - 1] = bi;
                        val[i] = tv;     idx[i] = ti;
                    }
                }
            }
            __syncthreads();   // protect ds before next pass / next macro-tile
        }
    }

    // concat the two half-lists directly into g_cand (no merge pass)
    {
        int pos = (n << 10) + p0 + sp;
        int* cl = g_cand + (size_t)pos * KC + sh * KT;
#pragma unroll
        for (int k = 0; k < KT; k++) cl[k] = idx[k];
    }
}

// ---------------------------------------------------------------------------
// Phase 2: exact fp32 rescore. Block = 32 p-contiguous positions (same n);
// x staged into smem via coalesced row reads; warp rescores 4 positions.
#define RSTR 516                         // floats per staged p-row (16B-aligned)
#define SMEM_R (32 * RSTR * 4 + 64)      // xs + red[8]

__global__ void __launch_bounds__(256) k_rescore(const float* __restrict__ x,
                                                 const float* __restrict__ cb,
                                                 float* __restrict__ out) {
    extern __shared__ __align__(16) float xsm[];
    double* red = (double*)(xsm + 32 * RSTR);

    int tid = threadIdx.x, lane = tid & 31, w = tid >> 5;
    int pbase = blockIdx.x << 5;
    int n = pbase >> 10, p0 = pbase & 1023;
    const float* xb = x + (size_t)n * CC * PP + p0;

    // stage x[n][:, p0:p0+32] -> xsm[p][c] (stride RSTR)
#pragma unroll 8
    for (int j = 0; j < 64; j++) {
        int c = (j << 3) + w;
        xsm[lane * RSTR + c] = xb[(size_t)c * PP + lane];
    }
    __syncthreads();

    double wsum = 0.0;
#pragma unroll
    for (int q = 0; q < 4; q++) {
        int pl = (w << 2) + q;
        int pos = pbase + pl;
        const float* xr_s = xsm + pl * RSTR;

        float4 xr[4];
#pragma unroll
        for (int j = 0; j < 4; j++) xr[j] = *(const float4*)(xr_s + (j << 7) + (lane << 2));

        float x2 = 0.f;
#pragma unroll
        for (int j = 0; j < 4; j++) {
            x2 = fmaf(xr[j].x, xr[j].x, x2);
            x2 = fmaf(xr[j].y, xr[j].y, x2);
            x2 = fmaf(xr[j].z, xr[j].z, x2);
            x2 = fmaf(xr[j].w, xr[j].w, x2);
        }
#pragma unroll
        for (int off = 16; off > 0; off >>= 1) x2 += __shfl_xor_sync(~0u, x2, off);

        float topk[NK];
#pragma unroll
        for (int i = 0; i < NK; i++) topk[i] = CUDART_INF_F;
        float minv = CUDART_INF_F;
        int   mini = 0x7FFFFFFF;

        const int* cl = g_cand + (size_t)pos * KC;
        for (int k = 0; k < KC; k++) {
            int s = __ldg(cl + k);
            const float* cr = cb + (size_t)s * CC;
            float xc = 0.f;
#pragma unroll
            for (int j = 0; j < 4; j++) {
                float4 c4 = *(const float4*)(cr + (j << 7) + (lane << 2));
                xc = fmaf(xr[j].x, c4.x, xc);
                xc = fmaf(xr[j].y, c4.y, xc);
                xc = fmaf(xr[j].z, c4.z, xc);
                xc = fmaf(xr[j].w, c4.w, xc);
            }
#pragma unroll
            for (int off = 16; off > 0; off >>= 1) xc += __shfl_xor_sync(~0u, xc, off);

            float d = __fadd_rn(__fadd_rn(x2, g_c2[s]), __fmul_rn(-2.0f, xc));
            if (d < minv || (d == minv && s < mini)) { minv = d; mini = s; }
            if (d < topk[NK - 1]) {
                topk[NK - 1] = d;
#pragma unroll
                for (int i = NK - 1; i > 0; --i) {
                    float lo = fminf(topk[i - 1], topk[i]);
                    float hi = fmaxf(topk[i - 1], topk[i]);
                    topk[i - 1] = lo; topk[i] = hi;
                }
            }
        }

        float ws = 0.f;
#pragma unroll
        for (int k = 0; k < NK; k++) ws = fmaf(topk[k], expf(-(float)k), ws);

        if (lane == 0) {
            out[2 + pos] = (float)mini;
            g_idx[pos]   = mini;
            wsum += (double)ws;
        }
    }

    if (lane == 0) red[w] = wsum;
    __syncthreads();
    if (tid == 0) {
        double sum = 0.0;
        for (int i = 0; i < 8; i++) sum += red[i];
        atomicAdd(&g_acc_cb, sum);
    }
}

// ---------------------------------------------------------------------------
__global__ void k_output(const float* __restrict__ x,
                         const float* __restrict__ cb,
                         float* __restrict__ out) {
    int pg = blockIdx.x;
    int n  = pg >> 5;
    int p0 = (pg & 31) << 5;
    int c0 = blockIdx.y << 7;

    __shared__ float sm[32 * 133];
    __shared__ int   sidx[32];
    __shared__ double rs[256];
    int tid = threadIdx.x;

    if (tid < 32) sidx[tid] = g_idx[(n << 10) + p0 + tid];
    __syncthreads();

#pragma unroll
    for (int i = 0; i < 4; i++) {
        int v = tid + (i << 8);
        int rr = v >> 5, c4 = (v & 31) << 2;
        float4 q = *(const float4*)(cb + (size_t)sidx[rr] * CC + c0 + c4);
        float* dst = &sm[rr * 133 + c4];
        dst[0] = q.x; dst[1] = q.y; dst[2] = q.z; dst[3] = q.w;
    }
    __syncthreads();

    int pl = tid & 31;
    int cb8 = tid >> 5;
    float fsum = 0.f;
    float* outv = out + 2 + NB * PP;

#pragma unroll
    for (int i = 0; i < 16; i++) {
        int cl = cb8 + (i << 3);
        float xq = sm[pl * 133 + cl];
        size_t gi = ((size_t)(n * CC + c0 + cl)) * PP + p0 + pl;
        float xv = __ldg(x + gi);
        float df = __fsub_rn(xv, xq);
        fsum = fmaf(df, df, fsum);
        outv[gi] = __fadd_rn(xv, __fsub_rn(xq, xv));
    }

    rs[tid] = (double)fsum;
    __syncthreads();
    for (int off = 128; off > 0; off >>= 1) {
        if (tid < off) rs[tid] += rs[tid + off];
        __syncthreads();
    }
    if (tid == 0) atomicAdd(&g_acc_commit, rs[0]);
}

// ---------------------------------------------------------------------------
__global__ void k_final(float* __restrict__ out) {
    out[0] = (float)(g_acc_cb     / (double)((size_t)NB * SS * PP));
    out[1] = (float)(g_acc_commit / (double)((size_t)NB * CC * PP));
}

// ---------------------------------------------------------------------------
extern "C" void kernel_launch(void* const* d_in, const int* in_sizes, int n_in,
                              void* d_out, int out_size) {
    const float* x  = (const float*)d_in[0];
    const float* cb = (const float*)d_in[1];
    if (n_in >= 2 && in_sizes[0] == SS * CC) {
        x  = (const float*)d_in[1];
        cb = (const float*)d_in[0];
    }
    float* out = (float*)d_out;
    (void)out_size;

    cudaFuncSetAttribute(k_fused, cudaFuncAttributeMaxDynamicSharedMemorySize, SM_TOTAL);
    cudaFuncSetAttribute(k_rescore, cudaFuncAttributeMaxDynamicSharedMemorySize, SMEM_R);

    k_prep_x<<<NB * CC * PP / 1024, 256>>>(x);
    k_prep_cb<<<SS, 128>>>(cb);
    k_fused<<<dim3(PP / 128, NB), 256, SM_TOTAL>>>();
    k_rescore<<<NB * PP / 32, 256, SMEM_R>>>(x, cb, out);
    k_output<<<dim3(1024, 4), 256>>>(x, cb, out);
    k_final<<<1, 1>>>(out);
}

// round 17
// speedup vs baseline: 1.0943x; 1.0943x over previous
#include <cuda_runtime.h>
#include <cuda_fp16.h>
#include <math_constants.h>
#include <cstdint>
#include <cstddef>

#define NB 32
#define CC 512
#define PP 1024
#define SS 2048
#define NK 10
#define KC 10     // candidates per position (= 2 x KT)
#define KT 5      // per-thread list depth

#define XSS 136   // x smem tile row stride (fp16)
#define CBS 40    // cb smem tile row stride (fp16)

// static device scratch
__device__ __half g_xh[(size_t)NB * CC * PP];    // fp16 x, layout [n][c][p]
__device__ __half g_cbh[(size_t)SS * CC];        // fp16 cb, [s][c]
__device__ float  g_xt[(size_t)NB * PP * CC];    // fp32 x transposed [n][p][c]
__device__ float  g_c2[SS];
__device__ int    g_cand[(size_t)NB * PP * KC];  // approx top-KC indices
__device__ int    g_idx[NB * PP];
__device__ double g_acc_cb;
__device__ double g_acc_commit;

// ---------------------------------------------------------------------------
__device__ __forceinline__ uint32_t cvta_s(const void* p) {
    return (uint32_t)__cvta_generic_to_shared(p);
}
__device__ __forceinline__ void cpa16(uint32_t d, const void* s) {
    asm volatile("cp.async.ca.shared.global [%0],[%1],16;" ::"r"(d), "l"(s));
}
__device__ __forceinline__ void cpcommit() {
    asm volatile("cp.async.commit_group;");
}
__device__ __forceinline__ void cpwait1() {
    asm volatile("cp.async.wait_group 1;");
}
__device__ __forceinline__ void cpwait0() {
    asm volatile("cp.async.wait_group 0;");
}
__device__ __forceinline__ void ldsm4t(uint32_t* d, uint32_t a) {
    asm volatile("ldmatrix.sync.aligned.m8n8.x4.trans.shared.b16 {%0,%1,%2,%3},[%4];"
                 : "=r"(d[0]), "=r"(d[1]), "=r"(d[2]), "=r"(d[3]) : "r"(a));
}
__device__ __forceinline__ void ldsm4(uint32_t* d, uint32_t a) {
    asm volatile("ldmatrix.sync.aligned.m8n8.x4.shared.b16 {%0,%1,%2,%3},[%4];"
                 : "=r"(d[0]), "=r"(d[1]), "=r"(d[2]), "=r"(d[3]) : "r"(a));
}
// fp16-accumulate mma: D,C = 2 x .f16x2 regs
__device__ __forceinline__ void mma_f16a(uint32_t* c, const uint32_t* a, const uint32_t* b) {
    asm volatile("mma.sync.aligned.m16n8k16.row.col.f16.f16.f16.f16 "
                 "{%0,%1},{%2,%3,%4,%5},{%6,%7},{%0,%1};"
                 : "+r"(c[0]), "+r"(c[1])
                 : "r"(a[0]), "r"(a[1]), "r"(a[2]), "r"(a[3]), "r"(b[0]), "r"(b[1]));
}

// ---------------------------------------------------------------------------
// x prep: fp16 copy (same [n][c][p] layout) + fp32 transpose to [n][p][c]
__global__ void k_prep_x(const float* __restrict__ x) {
    __shared__ float sh[64][65];
    int tid = threadIdx.x;
    int p0 = blockIdx.x << 6, c0 = blockIdx.y << 6, n = blockIdx.z;
    const float* xb = x + ((size_t)n * CC + c0) * PP + p0;
#pragma unroll
    for (int i = 0; i < 4; i++) {
        int idx = tid + (i << 8);
        int row = idx >> 4, q = idx & 15;
        float4 v = *(const float4*)(xb + (size_t)row * PP + (q << 2));
        __half2 h01 = __floats2half2_rn(v.x, v.y);
        __half2 h23 = __floats2half2_rn(v.z, v.w);
        size_t off = ((size_t)(n * CC + c0 + row)) * PP + p0 + (q << 2);
        *(__half2*)(g_xh + off)     = h01;
        *(__half2*)(g_xh + off + 2) = h23;
        sh[(q << 2) + 0][row] = v.x;
        sh[(q << 2) + 1][row] = v.y;
        sh[(q << 2) + 2][row] = v.z;
        sh[(q << 2) + 3][row] = v.w;
    }
    __syncthreads();
    size_t ob = ((size_t)n * PP + p0) * CC + c0;
#pragma unroll
    for (int i = 0; i < 4; i++) {
        int idx = tid + (i << 8);
        int pr = idx >> 4, cq = idx & 15;
        float4 w = make_float4(sh[pr][(cq << 2) + 0], sh[pr][(cq << 2) + 1],
                               sh[pr][(cq << 2) + 2], sh[pr][(cq << 2) + 3]);
        *(float4*)(g_xt + ob + (size_t)pr * CC + (cq << 2)) = w;
    }
}

// cb prep: fp16 copy + c2 + zero accumulators
__global__ void k_prep_cb(const float* __restrict__ cb) {
    __shared__ float sm[128];
    int s = blockIdx.x, t = threadIdx.x;
    size_t base = (size_t)s * CC + t * 4;
    float4 v = *(const float4*)(cb + base);
    float a = fmaf(v.x, v.x, fmaf(v.y, v.y, fmaf(v.z, v.z, __fmul_rn(v.w, v.w))));
    __half2 h01 = __floats2half2_rn(v.x, v.y);
    __half2 h23 = __floats2half2_rn(v.z, v.w);
    *(__half2*)(g_cbh + base)     = h01;
    *(__half2*)(g_cbh + base + 2) = h23;
    sm[t] = a;
    __syncthreads();
    for (int off = 64; off > 0; off >>= 1) {
        if (t < off) sm[t] += sm[t + off];
        __syncthreads();
    }
    if (t == 0) {
        g_c2[s] = sm[0];
        if (s == 0) { g_acc_cb = 0.0; g_acc_commit = 0.0; }
    }
}

// ---------------------------------------------------------------------------
// Phase 1: fp16 GEMM (fp16 acc), warp grid 2(p) x 4(s), s-macro-tile 256.
// 256 threads, 2 CTAs/SM, 2-stage cp.async pipeline. fp16 [p][s] ds handoff.
// smem (bytes):
#define SM_XH   0        // 2 x fp16[32][136] = 17408
#define SM_CH   17408    // 2 x fp16[256][40] = 40960
#define SM_C2   58368    // float[256] = 1024
#define SM_DS   59392    // __half[128][66] = 16896 (raw xc pairs, [p][s])
#define SM_TOTAL 76288
#define XSTG 8704
#define CSTG 20480
#define DSH 66

__global__ void __launch_bounds__(256, 2) k_fused() {
    extern __shared__ __align__(16) char smem[];
    float*  c2s = (float*)(smem + SM_C2);
    __half* dsh = (__half*)(smem + SM_DS);

    int n = blockIdx.y, p0 = blockIdx.x << 7;
    int tid = threadIdx.x, lid = tid & 31, wid = tid >> 5;
    int wm = wid & 1, wn = wid >> 1;       // 2 p-strips x 4 s-strips
    int sp = tid & 127, sh = tid >> 7;

    const __half* xh = g_xh + (size_t)n * CC * PP;

    int g8 = lid >> 3, r8 = lid & 7;
    int aoff = ((g8 >> 1) * 8 + r8) * XSS + (g8 & 1) * 8 + wm * 64;
    int boff = ((g8 >> 1) * 8 + r8) * CBS + (g8 & 1) * 8;

    uint32_t xs_b = cvta_s(smem + SM_XH);
    uint32_t cb_b = cvta_s(smem + SM_CH);

    // x stage fill: 8192 B -> 2 x 16B per thread
    int xrow0 = tid >> 4,          xch0 = (tid & 15) << 3;
    int xrow1 = (tid + 256) >> 4,  xch1 = xch0;
    uint32_t dst_x0 = xs_b + (uint32_t)(xrow0 * XSS + xch0) * 2;
    uint32_t dst_x1 = xs_b + (uint32_t)(xrow1 * XSS + xch1) * 2;
    // cb stage fill: 256 rows x 32 k = 16384 B -> 4 x 16B per thread
    int crow = tid >> 2, cch = (tid & 3) << 3;
    uint32_t dst_c0 = cb_b + (uint32_t)((crow +   0) * CBS + cch) * 2;
    uint32_t dst_c1 = cb_b + (uint32_t)((crow +  64) * CBS + cch) * 2;
    uint32_t dst_c2 = cb_b + (uint32_t)((crow + 128) * CBS + cch) * 2;
    uint32_t dst_c3 = cb_b + (uint32_t)((crow + 192) * CBS + cch) * 2;

    auto issue = [&](int G) {                 // G in [0,128)
        int stp = G >> 4, kcp = G & 15, stg = G & 1;
        int k0 = kcp << 5, s0g = stp << 8;
        uint32_t xo = stg ? XSTG : 0u, co = stg ? CSTG : 0u;
        cpa16(dst_x0 + xo, xh + (size_t)(k0 + xrow0) * PP + p0 + xch0);
        cpa16(dst_x1 + xo, xh + (size_t)(k0 + xrow1) * PP + p0 + xch1);
        cpa16(dst_c0 + co, g_cbh + (size_t)(s0g + crow +   0) * CC + k0 + cch);
        cpa16(dst_c1 + co, g_cbh + (size_t)(s0g + crow +  64) * CC + k0 + cch);
        cpa16(dst_c2 + co, g_cbh + (size_t)(s0g + crow + 128) * CC + k0 + cch);
        cpa16(dst_c3 + co, g_cbh + (size_t)(s0g + crow + 192) * CC + k0 + cch);
        cpcommit();
    };

    float val[KT];
    int   idx[KT];
#pragma unroll
    for (int i = 0; i < KT; i++) { val[i] = CUDART_INF_F; idx[i] = 0; }

    issue(0);
    issue(1);

    for (int st = 0; st < 8; ++st) {
        int s0 = st << 8;
        uint32_t acc[4][8][2];
#pragma unroll
        for (int mt = 0; mt < 4; mt++)
#pragma unroll
            for (int nt = 0; nt < 8; nt++) { acc[mt][nt][0] = 0u; acc[mt][nt][1] = 0u; }

        for (int kc = 0; kc < 16; ++kc) {
            int gch = (st << 4) + kc;
            if (gch == 127) cpwait0(); else cpwait1();
            __syncthreads();
            if (kc == 0) c2s[tid] = g_c2[s0 + tid];   // 256 threads, 256 values

            uint32_t xo = (gch & 1) ? XSTG : 0u, co = (gch & 1) ? CSTG : 0u;
#pragma unroll
            for (int ks = 0; ks < 2; ks++) {
                int kb = ks << 4;
                uint32_t Ah[4][4];
#pragma unroll
                for (int mt = 0; mt < 4; mt++)
                    ldsm4t(Ah[mt], xs_b + xo + (uint32_t)(kb * XSS + aoff + mt * 16) * 2);
#pragma unroll
                for (int bg = 0; bg < 4; bg++) {
                    uint32_t Bf[4];
                    int n0 = wn * 64 + bg * 16;
                    ldsm4(Bf, cb_b + co + (uint32_t)(n0 * CBS + kb + boff) * 2);
#pragma unroll
                    for (int q = 0; q < 2; q++) {
                        int nt = bg * 2 + q;
#pragma unroll
                        for (int mt = 0; mt < 4; mt++)
                            mma_f16a(acc[mt][nt], Ah[mt], &Bf[q * 2]);
                    }
                }
            }
            __syncthreads();
            if (gch + 2 < 128) issue(gch + 2);
        }

        // epilogue + scan in 4 passes of 64 s-cols (dsh: [128 p][64 s] fp16)
#pragma unroll
        for (int pass = 0; pass < 4; ++pass) {
            if (wn == pass) {
#pragma unroll
                for (int mt = 0; mt < 4; mt++) {
                    int pb = wm * 64 + mt * 16 + (lid >> 2);
#pragma unroll
                    for (int nt = 0; nt < 8; nt++) {
                        int sb = nt * 8 + ((lid & 3) << 1);
                        *(uint32_t*)&dsh[pb * DSH + sb]       = acc[mt][nt][0];
                        *(uint32_t*)&dsh[(pb + 8) * DSH + sb] = acc[mt][nt][1];
                    }
                }
            }
            __syncthreads();
            const uint32_t* row = (const uint32_t*)(dsh + sp * DSH) + (sh << 4);
            int sbase = s0 + (pass << 6) + (sh << 5);
            int cbase = (pass << 6) + (sh << 5);
#pragma unroll 4
            for (int k = 0; k < 16; k++) {
                uint32_t w = row[k];
                float2 f = __half22float2(*(__half2*)&w);
                float v0 = __fmaf_rn(-2.0f, f.x, c2s[cbase + 2 * k]);
                float v1 = __fmaf_rn(-2.0f, f.y, c2s[cbase + 2 * k + 1]);
                if (v0 < val[KT - 1]) {
                    val[KT - 1] = v0; idx[KT - 1] = sbase + 2 * k;
#pragma unroll
                    for (int i = KT - 1; i > 0; --i) {
                        bool sw = val[i - 1] > val[i];
                        float tv = sw ? val[i - 1] : val[i];
                        float bv = sw ? val[i] : val[i - 1];
                        int   ti = sw ? idx[i - 1] : idx[i];
                        int   bi = sw ? idx[i] : idx[i - 1];
                        val[i - 1] = bv; idx[i - 1] = bi;
                        val[i] = tv;     idx[i] = ti;
                    }
                }
                if (v1 < val[KT - 1]) {
                    val[KT - 1] = v1; idx[KT - 1] = sbase + 2 * k + 1;
#pragma unroll
                    for (int i = KT - 1; i > 0; --i) {
                        bool sw = val[i - 1] > val[i];
                        float tv = sw ? val[i - 1] : val[i];
                        float bv = sw ? val[i] : val[i - 1];
                        int   ti = sw ? idx[i - 1] : idx[i];
                        int   bi = sw ? idx[i] : idx[i - 1];
                        val[i - 1] = bv; idx[i - 1] = bi;
                        val[i] = tv;     idx[i] = ti;
                    }
                }
            }
            __syncthreads();   // protect dsh before next pass / macro-tile
        }
    }

    // concat the two half-lists directly into g_cand (no merge pass)
    {
        int pos = (n << 10) + p0 + sp;
        int* cl = g_cand + (size_t)pos * KC + sh * KT;
#pragma unroll
        for (int k = 0; k < KT; k++) cl[k] = idx[k];
    }
}

// ---------------------------------------------------------------------------
// Phase 2: exact fp32 rescore of KC candidates; warp per position (R15 form).
__global__ void __launch_bounds__(256) k_rescore(const float* __restrict__ cb,
                                                 float* __restrict__ out) {
    __shared__ double red[8];
    int tid = threadIdx.x, lane = tid & 31, w = tid >> 5;
    int pos = (blockIdx.x << 3) + w;

    const float* xt = g_xt + (size_t)pos * CC;
    float4 xr[4];
#pragma unroll
    for (int j = 0; j < 4; j++) xr[j] = *(const float4*)(xt + (j << 7) + (lane << 2));

    float x2 = 0.f;
#pragma unroll
    for (int j = 0; j < 4; j++) {
        x2 = fmaf(xr[j].x, xr[j].x, x2);
        x2 = fmaf(xr[j].y, xr[j].y, x2);
        x2 = fmaf(xr[j].z, xr[j].z, x2);
        x2 = fmaf(xr[j].w, xr[j].w, x2);
    }
#pragma unroll
    for (int off = 16; off > 0; off >>= 1) x2 += __shfl_xor_sync(~0u, x2, off);

    float topk[NK];
#pragma unroll
    for (int i = 0; i < NK; i++) topk[i] = CUDART_INF_F;
    float minv = CUDART_INF_F;
    int   mini = 0x7FFFFFFF;

    const int* cl = g_cand + (size_t)pos * KC;
    for (int k = 0; k < KC; k++) {
        int s = __ldg(cl + k);
        const float* cr = cb + (size_t)s * CC;
        float xc = 0.f;
#pragma unroll
        for (int j = 0; j < 4; j++) {
            float4 c4 = *(const float4*)(cr + (j << 7) + (lane << 2));
            xc = fmaf(xr[j].x, c4.x, xc);
            xc = fmaf(xr[j].y, c4.y, xc);
            xc = fmaf(xr[j].z, c4.z, xc);
            xc = fmaf(xr[j].w, c4.w, xc);
        }
#pragma unroll
        for (int off = 16; off > 0; off >>= 1) xc += __shfl_xor_sync(~0u, xc, off);

        float d = __fadd_rn(__fadd_rn(x2, g_c2[s]), __fmul_rn(-2.0f, xc));
        if (d < minv || (d == minv && s < mini)) { minv = d; mini = s; }
        if (d < topk[NK - 1]) {
            topk[NK - 1] = d;
#pragma unroll
            for (int i = NK - 1; i > 0; --i) {
                float lo = fminf(topk[i - 1], topk[i]);
                float hi = fmaxf(topk[i - 1], topk[i]);
                topk[i - 1] = lo; topk[i] = hi;
            }
        }
    }

    float ws = 0.f;
#pragma unroll
    for (int k = 0; k < NK; k++) ws = fmaf(topk[k], expf(-(float)k), ws);

    if (lane == 0) {
        out[2 + pos] = (float)mini;
        g_idx[pos]   = mini;
        red[w] = (double)ws;
    }
    __syncthreads();
    if (tid == 0) {
        double sum = 0.0;
        for (int i = 0; i < 8; i++) sum += red[i];
        atomicAdd(&g_acc_cb, sum);
    }
}

// ---------------------------------------------------------------------------
__global__ void k_output(const float* __restrict__ x,
                         const float* __restrict__ cb,
                         float* __restrict__ out) {
    int pg = blockIdx.x;
    int n  = pg >> 5;
    int p0 = (pg & 31) << 5;
    int c0 = blockIdx.y << 7;

    __shared__ float sm[32 * 133];
    __shared__ int   sidx[32];
    __shared__ double rs[256];
    int tid = threadIdx.x;

    if (tid < 32) sidx[tid] = g_idx[(n << 10) + p0 + tid];
    __syncthreads();

#pragma unroll
    for (int i = 0; i < 4; i++) {
        int v = tid + (i << 8);
        int rr = v >> 5, c4 = (v & 31) << 2;
        float4 q = *(const float4*)(cb + (size_t)sidx[rr] * CC + c0 + c4);
        float* dst = &sm[rr * 133 + c4];
        dst[0] = q.x; dst[1] = q.y; dst[2] = q.z; dst[3] = q.w;
    }
    __syncthreads();

    int pl = tid & 31;
    int cb8 = tid >> 5;
    float fsum = 0.f;
    float* outv = out + 2 + NB * PP;

#pragma unroll
    for (int i = 0; i < 16; i++) {
        int cl = cb8 + (i << 3);
        float xq = sm[pl * 133 + cl];
        size_t gi = ((size_t)(n * CC + c0 + cl)) * PP + p0 + pl;
        float xv = __ldg(x + gi);
        float df = __fsub_rn(xv, xq);
        fsum = fmaf(df, df, fsum);
        outv[gi] = __fadd_rn(xv, __fsub_rn(xq, xv));
    }

    rs[tid] = (double)fsum;
    __syncthreads();
    for (int off = 128; off > 0; off >>= 1) {
        if (tid < off) rs[tid] += rs[tid + off];
        __syncthreads();
    }
    if (tid == 0) atomicAdd(&g_acc_commit, rs[0]);
}

// ---------------------------------------------------------------------------
__global__ void k_final(float* __restrict__ out) {
    out[0] = (float)(g_acc_cb     / (double)((size_t)NB * SS * PP));
    out[1] = (float)(g_acc_commit / (double)((size_t)NB * CC * PP));
}

// ---------------------------------------------------------------------------
extern "C" void kernel_launch(void* const* d_in, const int* in_sizes, int n_in,
                              void* d_out, int out_size) {
    const float* x  = (const float*)d_in[0];
    const float* cb = (const float*)d_in[1];
    if (n_in >= 2 && in_sizes[0] == SS * CC) {
        x  = (const float*)d_in[1];
        cb = (const float*)d_in[0];
    }
    float* out = (float*)d_out;
    (void)out_size;

    cudaFuncSetAttribute(k_fused, cudaFuncAttributeMaxDynamicSharedMemorySize, SM_TOTAL);

    k_prep_x<<<dim3(PP / 64, CC / 64, NB), 256>>>(x);
    k_prep_cb<<<SS, 128>>>(cb);
    k_fused<<<dim3(PP / 128, NB), 256, SM_TOTAL>>>();
    k_rescore<<<NB * PP / 8, 256>>>(cb, out);
    k_output<<<dim3(1024, 4), 256>>>(x, cb, out);
    k_final<<<1, 1>>>(out);
}